// round 13
// baseline (speedup 1.0000x reference)
#include <cuda_runtime.h>
#include <cuda_bf16.h>
#include <cstdint>
#include <math.h>

#define N_NODES 100000
#define HID     128
#define NUM_CLS 20
#define N_EDGES 625000
#define SCAN_BS 256
#define SCAN_NB ((N_NODES + SCAN_BS - 1) / SCAN_BS)   // 391

// ---------------- scratch (static device globals; no allocation) ----------------
__device__ float d_summed[N_NODES * HID];          // holds aggr (mean)
__device__ int   d_counts[N_NODES];
__device__ int   d_starts[N_NODES];
__device__ int   d_cursor[N_NODES];
__device__ int   d_bucket[N_EDGES];
__device__ int   d_bsum[512];
__device__ __nv_bfloat16 d_Bhi[128 * 256];         // weight^T bf16-hi  [n][k]
__device__ __nv_bfloat16 d_Blo[128 * 256];         // weight^T bf16-lo  [n][k]
__device__ float d_Wn[HID * NUM_CLS];              // col-normalized classifier weight

__device__ __forceinline__ uint32_t smem_u32(const void* p) {
    uint32_t a;
    asm("{ .reg .u64 t; cvta.to.shared.u64 t, %1; cvt.u32.u64 %0, t; }" : "=r"(a) : "l"(p));
    return a;
}

// ---------------- CSR build: histogram + scan + bucket fill ----------------
__global__ void zero_counts_kernel() {
    int i = blockIdx.x * blockDim.x + threadIdx.x;
    if (i < N_NODES) d_counts[i] = 0;
}

__global__ void hist_kernel(const int* __restrict__ ei) {
    int e = blockIdx.x * blockDim.x + threadIdx.x;
    if (e < N_EDGES) atomicAdd(&d_counts[__ldg(&ei[N_EDGES + e])], 1);
}

__global__ void scan1_kernel() {
    __shared__ int s[SCAN_BS];
    int i = blockIdx.x * SCAN_BS + threadIdx.x;
    int v = (i < N_NODES) ? d_counts[i] : 0;
    s[threadIdx.x] = v;
    __syncthreads();
    for (int off = 1; off < SCAN_BS; off <<= 1) {
        int t = (threadIdx.x >= off) ? s[threadIdx.x - off] : 0;
        __syncthreads();
        s[threadIdx.x] += t;
        __syncthreads();
    }
    if (i < N_NODES) d_starts[i] = s[threadIdx.x] - v;   // exclusive within block
    if (threadIdx.x == SCAN_BS - 1) d_bsum[blockIdx.x] = s[SCAN_BS - 1];
}

// scan2 fused here: each block reduces bsum[0..blockIdx.x) itself.
__global__ void scan3_kernel() {
    __shared__ int red[SCAN_BS];
    int t = threadIdx.x;
    int lim = blockIdx.x;
    int p = 0;
    for (int j = t; j < lim; j += SCAN_BS) p += d_bsum[j];
    red[t] = p;
    __syncthreads();
    #pragma unroll
    for (int off = SCAN_BS / 2; off > 0; off >>= 1) {
        if (t < off) red[t] += red[t + off];
        __syncthreads();
    }
    int base = red[0];
    int i = blockIdx.x * SCAN_BS + t;
    if (i < N_NODES) {
        int v = d_starts[i] + base;
        d_starts[i] = v;
        d_cursor[i] = v;
    }
}

__global__ void fill_kernel(const int* __restrict__ ei) {
    int e = blockIdx.x * blockDim.x + threadIdx.x;
    if (e < N_EDGES) {
        int dst = __ldg(&ei[N_EDGES + e]);
        int pos = atomicAdd(&d_cursor[dst], 1);
        d_bucket[pos] = __ldg(&ei[e]);
    }
}

// ---------------- aggregate: warp per node, lane-parallel index fetch ----------------
__global__ __launch_bounds__(256)
void agg_kernel(const float* __restrict__ x) {
    int gw   = (blockIdx.x * blockDim.x + threadIdx.x) >> 5;
    int lane = threadIdx.x & 31;
    if (gw >= N_NODES) return;
    int deg   = __ldg(&d_counts[gw]);
    int start = __ldg(&d_starts[gw]);

    // one coalesced load fetches up to 32 neighbor indices (covers ~all nodes)
    int nb = min(deg, 32);
    int myidx = (lane < nb) ? __ldg(&d_bucket[start + lane]) : 0;

    float4 acc = make_float4(0.f, 0.f, 0.f, 0.f);
    int i = 0;
    for (; i + 4 <= nb; i += 4) {
        int s0 = __shfl_sync(0xffffffffu, myidx, i);
        int s1 = __shfl_sync(0xffffffffu, myidx, i + 1);
        int s2 = __shfl_sync(0xffffffffu, myidx, i + 2);
        int s3 = __shfl_sync(0xffffffffu, myidx, i + 3);
        float4 v0 = __ldg(reinterpret_cast<const float4*>(x + (size_t)s0 * HID) + lane);
        float4 v1 = __ldg(reinterpret_cast<const float4*>(x + (size_t)s1 * HID) + lane);
        float4 v2 = __ldg(reinterpret_cast<const float4*>(x + (size_t)s2 * HID) + lane);
        float4 v3 = __ldg(reinterpret_cast<const float4*>(x + (size_t)s3 * HID) + lane);
        acc.x += v0.x + v1.x + v2.x + v3.x;
        acc.y += v0.y + v1.y + v2.y + v3.y;
        acc.z += v0.z + v1.z + v2.z + v3.z;
        acc.w += v0.w + v1.w + v2.w + v3.w;
    }
    for (; i < nb; i++) {
        int s = __shfl_sync(0xffffffffu, myidx, i);
        float4 v = __ldg(reinterpret_cast<const float4*>(x + (size_t)s * HID) + lane);
        acc.x += v.x; acc.y += v.y; acc.z += v.z; acc.w += v.w;
    }
    for (int j = 32; j < deg; j++) {            // rare tail (deg > 32)
        int s = __ldg(&d_bucket[start + j]);
        float4 v = __ldg(reinterpret_cast<const float4*>(x + (size_t)s * HID) + lane);
        acc.x += v.x; acc.y += v.y; acc.z += v.z; acc.w += v.w;
    }
    float inv = 1.f / (float)max(deg, 1);
    acc.x *= inv; acc.y *= inv; acc.z *= inv; acc.w *= inv;
    *reinterpret_cast<float4*>(&d_summed[(size_t)gw * HID + lane * 4]) = acc;
}

// ---------------- tiny prep kernels ----------------
__global__ void normw_kernel(const float* __restrict__ Wc) {
    int c = threadIdx.x;
    if (c >= NUM_CLS) return;
    float s = 0.f;
    for (int j = 0; j < HID; j++) {
        float v = Wc[j * NUM_CLS + c];
        s += v * v;
    }
    float inv = 1.f / fmaxf(sqrtf(s), 1e-12f);
    for (int j = 0; j < HID; j++)
        d_Wn[j * NUM_CLS + c] = Wc[j * NUM_CLS + c] * inv;
}

__global__ void prepB_kernel(const float* __restrict__ Wl, const float* __restrict__ Wr) {
    int n = blockIdx.x;
    int k = threadIdx.x;
    float w = (k < 128) ? Wl[k * 128 + n] : Wr[(k - 128) * 128 + n];
    __nv_bfloat16 hi = __float2bfloat16_rn(w);
    __nv_bfloat16 lo = __float2bfloat16_rn(w - __bfloat162float(hi));
    d_Bhi[n * 256 + k] = hi;
    d_Blo[n * 256 + k] = lo;
}

// ---------------- GEMM: mma.sync bf16-split, double-buffered, fused epilogue ----------
#define STAGE_BUF  24576
#define SM_AHI   0
#define SM_ALO   6144
#define SM_BHI   12288
#define SM_BLO   18432
#define SM_C     0
#define SM_WN    66048
#define SM_BIAS  76288
#define SM_PART  77312
#define GEMM_SMEM_BYTES 88064

__device__ __forceinline__ void mma_bf16(float* c, const uint32_t* a, uint32_t b0, uint32_t b1) {
    asm volatile("mma.sync.aligned.m16n8k16.row.col.f32.bf16.bf16.f32 "
                 "{%0,%1,%2,%3}, {%4,%5,%6,%7}, {%8,%9}, {%0,%1,%2,%3};"
                 : "+f"(c[0]), "+f"(c[1]), "+f"(c[2]), "+f"(c[3])
                 : "r"(a[0]), "r"(a[1]), "r"(a[2]), "r"(a[3]), "r"(b0), "r"(b1));
}
#define LDMX4(r, addr) \
    asm volatile("ldmatrix.sync.aligned.m8n8.x4.shared.b16 {%0,%1,%2,%3}, [%4];" \
                 : "=r"((r)[0]), "=r"((r)[1]), "=r"((r)[2]), "=r"((r)[3]) : "r"(addr))

__global__ __launch_bounds__(256, 2)
void gemm_mma_kernel(const float* __restrict__ x,
                     const float* __restrict__ bl,
                     float* __restrict__ out) {
    extern __shared__ char sm[];
    float* smf = reinterpret_cast<float*>(sm);
    const uint32_t sb32 = smem_u32(sm);
    const int tid  = threadIdx.x;
    const int wid  = tid >> 5;
    const int lane = tid & 31;
    const int g    = lane >> 2;
    const int tig  = lane & 3;
    const int warp_m = wid >> 1;
    const int warp_n = wid & 1;
    const int rbase = warp_m * 32;
    const int cbase = warp_n * 64;
    const int block_row = blockIdx.x * 128;

    const int lm_mat = lane >> 3;
    const int lm_rin = lane & 7;
    const uint32_t a_off0 = (uint32_t)(((rbase + lm_rin + (lm_mat & 1) * 8) * 24 + (lm_mat >> 1) * 8) * 2);
    const uint32_t a_off1 = a_off0 + 16 * 24 * 2;
    const uint32_t b_off  = (uint32_t)(((cbase + (lm_mat >> 1) * 8 + lm_rin) * 24 + (lm_mat & 1) * 8) * 2);

    const int a_row0 = tid >> 2;
    const int a_kq0  = tid & 3;
    const int a_row1 = (tid + 256) >> 2;
    const int a_kq1  = (tid + 256) & 3;
    const int b_row  = tid >> 1;
    const int b_half = tid & 1;

    for (int i = tid; i < HID * NUM_CLS; i += 256) smf[SM_WN / 4 + i] = d_Wn[i];
    if (tid < 128) smf[SM_BIAS / 4 + tid] = __ldg(&bl[tid]);
    __syncthreads();

    float acc[64];
    #pragma unroll
    for (int i = 0; i < 64; i++) acc[i] = 0.f;

    const int grow0 = block_row + a_row0;
    const int grow1 = block_row + a_row1;

    auto load_chunk = [&](int c, float4& av0, float4& av1, uint4& vh, uint4& vl) {
        const int kb = c * 16;
        const bool left = (c < 8);
        av0 = make_float4(0.f, 0.f, 0.f, 0.f);
        av1 = make_float4(0.f, 0.f, 0.f, 0.f);
        if (grow0 < N_NODES) {
            const float* base = left ? &d_summed[(size_t)grow0 * HID + kb]
                                     : &x[(size_t)grow0 * HID + (kb - 128)];
            av0 = __ldg(reinterpret_cast<const float4*>(base + a_kq0 * 4));
        }
        if (grow1 < N_NODES) {
            const float* base = left ? &d_summed[(size_t)grow1 * HID + kb]
                                     : &x[(size_t)grow1 * HID + (kb - 128)];
            av1 = __ldg(reinterpret_cast<const float4*>(base + a_kq1 * 4));
        }
        const char* gh = reinterpret_cast<const char*>(d_Bhi) + b_row * 512 + kb * 2 + b_half * 16;
        const char* gl = reinterpret_cast<const char*>(d_Blo) + b_row * 512 + kb * 2 + b_half * 16;
        vh = __ldg(reinterpret_cast<const uint4*>(gh));
        vl = __ldg(reinterpret_cast<const uint4*>(gl));
    };
    auto store_chunk = [&](int c, const float4& av0, const float4& av1,
                           const uint4& vh, const uint4& vl) {
        char* buf = sm + (c & 1) * STAGE_BUF;
        {
            const float4& a = av0;
            __nv_bfloat162 h01, h23, l01, l23;
            h01.x = __float2bfloat16_rn(a.x); h01.y = __float2bfloat16_rn(a.y);
            h23.x = __float2bfloat16_rn(a.z); h23.y = __float2bfloat16_rn(a.w);
            l01.x = __float2bfloat16_rn(a.x - __bfloat162float(h01.x));
            l01.y = __float2bfloat16_rn(a.y - __bfloat162float(h01.y));
            l23.x = __float2bfloat16_rn(a.z - __bfloat162float(h23.x));
            l23.y = __float2bfloat16_rn(a.w - __bfloat162float(h23.y));
            uint32_t off = (uint32_t)(a_row0 * 24 + a_kq0 * 4) * 2;
            *reinterpret_cast<__nv_bfloat162*>(buf + SM_AHI + off)     = h01;
            *reinterpret_cast<__nv_bfloat162*>(buf + SM_AHI + off + 4) = h23;
            *reinterpret_cast<__nv_bfloat162*>(buf + SM_ALO + off)     = l01;
            *reinterpret_cast<__nv_bfloat162*>(buf + SM_ALO + off + 4) = l23;
        }
        {
            const float4& a = av1;
            __nv_bfloat162 h01, h23, l01, l23;
            h01.x = __float2bfloat16_rn(a.x); h01.y = __float2bfloat16_rn(a.y);
            h23.x = __float2bfloat16_rn(a.z); h23.y = __float2bfloat16_rn(a.w);
            l01.x = __float2bfloat16_rn(a.x - __bfloat162float(h01.x));
            l01.y = __float2bfloat16_rn(a.y - __bfloat162float(h01.y));
            l23.x = __float2bfloat16_rn(a.z - __bfloat162float(h23.x));
            l23.y = __float2bfloat16_rn(a.w - __bfloat162float(h23.y));
            uint32_t off = (uint32_t)(a_row1 * 24 + a_kq1 * 4) * 2;
            *reinterpret_cast<__nv_bfloat162*>(buf + SM_AHI + off)     = h01;
            *reinterpret_cast<__nv_bfloat162*>(buf + SM_AHI + off + 4) = h23;
            *reinterpret_cast<__nv_bfloat162*>(buf + SM_ALO + off)     = l01;
            *reinterpret_cast<__nv_bfloat162*>(buf + SM_ALO + off + 4) = l23;
        }
        *reinterpret_cast<uint4*>(buf + SM_BHI + b_row * 48 + b_half * 16) = vh;
        *reinterpret_cast<uint4*>(buf + SM_BLO + b_row * 48 + b_half * 16) = vl;
    };

    {
        float4 av0, av1; uint4 vh, vl;
        load_chunk(0, av0, av1, vh, vl);
        store_chunk(0, av0, av1, vh, vl);
    }
    __syncthreads();

    for (int c = 0; c < 16; c++) {
        float4 av0, av1; uint4 vh, vl;
        if (c < 15) load_chunk(c + 1, av0, av1, vh, vl);

        const uint32_t bufb = sb32 + (uint32_t)((c & 1) * STAGE_BUF);
        #pragma unroll
        for (int p = 0; p < 3; p++) {
            const uint32_t sa  = bufb + ((p == 2) ? SM_ALO : SM_AHI);
            const uint32_t sbb = bufb + ((p == 1) ? SM_BLO : SM_BHI);
            uint32_t af0[4], af1[4];
            LDMX4(af0, sa + a_off0);
            LDMX4(af1, sa + a_off1);
            #pragma unroll
            for (int j2 = 0; j2 < 4; j2++) {
                uint32_t bf[4];
                LDMX4(bf, sbb + b_off + (uint32_t)(j2 * 16 * 24 * 2));
                mma_bf16(&acc[(0 * 8 + j2 * 2 + 0) * 4], af0, bf[0], bf[1]);
                mma_bf16(&acc[(1 * 8 + j2 * 2 + 0) * 4], af1, bf[0], bf[1]);
                mma_bf16(&acc[(0 * 8 + j2 * 2 + 1) * 4], af0, bf[2], bf[3]);
                mma_bf16(&acc[(1 * 8 + j2 * 2 + 1) * 4], af1, bf[2], bf[3]);
            }
        }
        if (c < 15) store_chunk(c + 1, av0, av1, vh, vl);
        __syncthreads();
    }

    #pragma unroll
    for (int mt = 0; mt < 2; mt++) {
        #pragma unroll
        for (int j = 0; j < 8; j++) {
            int r0  = rbase + mt * 16 + g;
            int col = cbase + j * 8 + tig * 2;
            const float* a4 = &acc[(mt * 8 + j) * 4];
            smf[SM_C / 4 + r0 * 129 + col]           = a4[0];
            smf[SM_C / 4 + r0 * 129 + col + 1]       = a4[1];
            smf[SM_C / 4 + (r0 + 8) * 129 + col]     = a4[2];
            smf[SM_C / 4 + (r0 + 8) * 129 + col + 1] = a4[3];
        }
    }
    __syncthreads();

    {
        int half = tid >> 7;
        int row  = tid & 127;
        int cb   = half * 64;
        float ss = 0.f;
        float a20[NUM_CLS];
        #pragma unroll
        for (int k = 0; k < NUM_CLS; k++) a20[k] = 0.f;

        #pragma unroll 4
        for (int j = 0; j < 64; j++) {
            int col = cb + j;
            float h = smf[SM_C / 4 + row * 129 + col] + smf[SM_BIAS / 4 + col];
            ss += h * h;
            const float4* wr = reinterpret_cast<const float4*>(&smf[SM_WN / 4 + col * NUM_CLS]);
            float4 w0 = wr[0], w1 = wr[1], w2 = wr[2], w3 = wr[3], w4 = wr[4];
            a20[0]  += h * w0.x; a20[1]  += h * w0.y; a20[2]  += h * w0.z; a20[3]  += h * w0.w;
            a20[4]  += h * w1.x; a20[5]  += h * w1.y; a20[6]  += h * w1.z; a20[7]  += h * w1.w;
            a20[8]  += h * w2.x; a20[9]  += h * w2.y; a20[10] += h * w2.z; a20[11] += h * w2.w;
            a20[12] += h * w3.x; a20[13] += h * w3.y; a20[14] += h * w3.z; a20[15] += h * w3.w;
            a20[16] += h * w4.x; a20[17] += h * w4.y; a20[18] += h * w4.z; a20[19] += h * w4.w;
        }
        if (half == 1) {
            float* pp = &smf[SM_PART / 4 + row * 21];
            pp[0] = ss;
            #pragma unroll
            for (int k = 0; k < NUM_CLS; k++) pp[1 + k] = a20[k];
        }
        __syncthreads();
        if (half == 0) {
            const float* pp = &smf[SM_PART / 4 + row * 21];
            ss += pp[0];
            #pragma unroll
            for (int k = 0; k < NUM_CLS; k++) a20[k] += pp[1 + k];
            int grow = block_row + row;
            if (grow < N_NODES) {
                float inv = 1.f / fmaxf(sqrtf(ss), 1e-12f);
                float* op = out + (size_t)grow * NUM_CLS;
                #pragma unroll
                for (int q = 0; q < 5; q++) {
                    float4 o;
                    o.x = a20[q * 4 + 0] * inv; o.y = a20[q * 4 + 1] * inv;
                    o.z = a20[q * 4 + 2] * inv; o.w = a20[q * 4 + 3] * inv;
                    *reinterpret_cast<float4*>(op + q * 4) = o;
                }
            }
        }
    }
}

// ---------------- launch ----------------
extern "C" void kernel_launch(void* const* d_in, const int* in_sizes, int n_in,
                              void* d_out, int out_size) {
    const float* x   = (const float*)d_in[0];
    const int*   ei  = (const int*)d_in[1];     // int32 (JAX demotes int64)
    const float* Wl  = (const float*)d_in[2];
    const float* bl  = (const float*)d_in[3];
    const float* Wr  = (const float*)d_in[4];
    const float* Wc  = (const float*)d_in[5];
    float*       out = (float*)d_out;

    cudaFuncSetAttribute(gemm_mma_kernel, cudaFuncAttributeMaxDynamicSharedMemorySize,
                         GEMM_SMEM_BYTES);

    const int EB = (N_EDGES + 255) / 256;
    zero_counts_kernel<<<SCAN_NB, SCAN_BS>>>();
    hist_kernel<<<EB, 256>>>(ei);
    scan1_kernel<<<SCAN_NB, SCAN_BS>>>();
    scan3_kernel<<<SCAN_NB, SCAN_BS>>>();   // scan2 fused in
    fill_kernel<<<EB, 256>>>(ei);
    normw_kernel<<<1, 32>>>(Wc);
    prepB_kernel<<<128, 256>>>(Wl, Wr);
    agg_kernel<<<(N_NODES * 32 + 255) / 256, 256>>>(x);
    gemm_mma_kernel<<<(N_NODES + 127) / 128, 256, GEMM_SMEM_BYTES>>>(x, bl, out);
}